// round 4
// baseline (speedup 1.0000x reference)
#include <cuda_runtime.h>
#include <cstdint>

// Problem constants
#define BB 2
#define QQ 10
#define CC 64
#define HH 256
#define WW 256
#define HWXY (HH * WW)            // 65536
#define KK 9
#define LL 64800                  // 180*360
#define NN (QQ * HWXY)            // 655360 per-b
#define BQ (BB * QQ)              // 20

// Channel-last scratch: g_xt[(bq*HW + hw)*64 + c]  == xt[(b*N + n)*64 + c]
__device__ float g_xt[(size_t)BQ * HWXY * CC];   // 335 MB

// ---------------------------------------------------------------------------
// Kernel 1: per-bq transpose (C=64, HW) -> (HW, C=64)
// block (32,8), grid (HW/32, 1, BQ)
// ---------------------------------------------------------------------------
__global__ void transpose_kernel(const float* __restrict__ x, float* __restrict__ xt)
{
    __shared__ float tile[CC][33];

    const int hw0 = blockIdx.x * 32;
    const size_t inbase = (size_t)blockIdx.z * CC * HWXY;

    // load 64 (c) rows x 32 (hw) cols, coalesced along hw
    #pragma unroll
    for (int r = threadIdx.y; r < CC; r += 8) {
        tile[r][threadIdx.x] = x[inbase + (size_t)r * HWXY + hw0 + threadIdx.x];
    }
    __syncthreads();

    // write 32 (n) rows x 64 (c) cols, coalesced along c (256B per n-row)
    const size_t outbase = ((size_t)blockIdx.z * HWXY + hw0) * CC;
    const int t  = threadIdx.y * 32 + threadIdx.x;   // 0..255
    const int c  = t & 63;
    const int ns = t >> 6;                            // 0..3
    #pragma unroll
    for (int j = 0; j < 8; j++) {
        const int n = j * 4 + ns;
        xt[outbase + (size_t)n * CC + c] = tile[c][n];  // smem stride 33: conflict-free
    }
}

// ---------------------------------------------------------------------------
// Kernel 2: fused gather + mean/max + attention + K-contraction
// one warp per (b, l); block = 256 threads = 8 consecutive l
// grid: (LL/8 = 8100, BB)
// ---------------------------------------------------------------------------
__global__ void __launch_bounds__(256)
fused_kernel(const float* __restrict__ xt,
             const void* __restrict__ idx_raw,  // (64800,9) int32 OR int64
             const float* __restrict__ att_w,   // (9,2,9)
             const float* __restrict__ att_b,   // (9,)
             const float* __restrict__ tc_w,    // (64,9)
             const float* __restrict__ tc_b,    // (64,)
             float* __restrict__ out)           // (B, 64, L)
{
    __shared__ float s_aw[KK * 2 * KK];  // 162
    __shared__ float s_ab[KK];

    const int tid = threadIdx.x;
    if (tid < KK * 2 * KK) s_aw[tid] = att_w[tid];
    if (tid < KK)          s_ab[tid] = att_b[tid];
    __syncthreads();

    // ---- dtype sniff: int64 values < 2^31 have zero high words at odd
    // 32-bit positions; int32 indices there are random in [0, 655360).
    const int* __restrict__ i32 = (const int*)idx_raw;
    const bool is64 = (i32[1] | i32[3] | i32[5] | i32[7] |
                       i32[9] | i32[11] | i32[13] | i32[15]) == 0;

    const int warp = tid >> 5;
    const int lane = tid & 31;
    const int l = blockIdx.x * 8 + warp;
    const int b = blockIdx.y;

    // gather indices: lanes 0..8 load, then broadcast
    int nk = 0;
    if (lane < KK) {
        const size_t pos = (size_t)l * KK + lane;
        nk = is64 ? (int)((const long long*)idx_raw)[pos] : i32[pos];
    }

    // each lane owns channels c0=2*lane, c0+1
    float2 v[KK];
    const float2* __restrict__ xt2 = (const float2*)xt;
    #pragma unroll
    for (int k = 0; k < KK; k++) {
        const int n = __shfl_sync(0xffffffffu, nk, k);
        v[k] = xt2[((size_t)b * NN + (size_t)n) * 32 + lane];  // 256B coalesced
    }

    // mean / max over C via butterfly
    float mean_s[KK], max_s[KK];
    #pragma unroll
    for (int k = 0; k < KK; k++) {
        float s = v[k].x + v[k].y;
        float m = fmaxf(v[k].x, v[k].y);
        #pragma unroll
        for (int o = 16; o; o >>= 1) {
            s += __shfl_xor_sync(0xffffffffu, s, o);
            m  = fmaxf(m, __shfl_xor_sync(0xffffffffu, m, o));
        }
        mean_s[k] = s * (1.0f / 64.0f);
        max_s[k]  = m;
    }

    // lanes 0..8 compute their attention gate; then broadcast scales
    float att = 0.0f;
    if (lane < KK) {
        float z = s_ab[lane];
        #pragma unroll
        for (int k = 0; k < KK; k++) {
            z = fmaf(mean_s[k], s_aw[lane * 18 + k],     z);
            z = fmaf(max_s[k],  s_aw[lane * 18 + 9 + k], z);
        }
        att = 1.0f / (1.0f + __expf(-z));
    }
    float scale[KK];
    #pragma unroll
    for (int k = 0; k < KK; k++) {
        scale[k] = 1.0f + __shfl_sync(0xffffffffu, att, k);
    }

    // output contraction over K for this lane's two channels
    const int c0 = lane * 2;
    float o0 = __ldg(&tc_b[c0]);
    float o1 = __ldg(&tc_b[c0 + 1]);
    #pragma unroll
    for (int k = 0; k < KK; k++) {
        o0 = fmaf(v[k].x * scale[k], __ldg(&tc_w[c0 * KK + k]),       o0);
        o1 = fmaf(v[k].y * scale[k], __ldg(&tc_w[(c0 + 1) * KK + k]), o1);
    }

    // out[(b*64 + c)*L + l]; 8 warps in block share sectors across consecutive l
    out[((size_t)(b * CC + c0)     ) * LL + l] = o0;
    out[((size_t)(b * CC + c0 + 1) ) * LL + l] = o1;
}

// ---------------------------------------------------------------------------
extern "C" void kernel_launch(void* const* d_in, const int* in_sizes, int n_in,
                              void* d_out, int out_size)
{
    const float* x     = (const float*)d_in[0];      // (20, 64, 256, 256)
    const void*  idx   = d_in[1];                    // (64800, 9) int32 or int64
    const float* att_w = (const float*)d_in[2];      // (9,2,9)
    const float* att_b = (const float*)d_in[3];      // (9,)
    const float* tc_w  = (const float*)d_in[4];      // (64,9)
    const float* tc_b  = (const float*)d_in[5];      // (64,)
    float*       out   = (float*)d_out;              // (2, 64, 180, 360)

    float* xt;
    cudaGetSymbolAddress((void**)&xt, g_xt);

    {
        dim3 grid(HWXY / 32, 1, BQ);
        dim3 block(32, 8);
        transpose_kernel<<<grid, block>>>(x, xt);
    }
    {
        dim3 grid(LL / 8, BB);
        fused_kernel<<<grid, 256>>>(xt, idx, att_w, att_b, tc_w, tc_b, out);
    }
}

// round 6
// speedup vs baseline: 1.6972x; 1.6972x over previous
#include <cuda_runtime.h>
#include <cstdint>

// Problem constants
#define BB 2
#define QQ 10
#define CC 64
#define HH 256
#define WW 256
#define HWXY (HH * WW)            // 65536
#define KK 9
#define LL 64800                  // 180*360
#define NN (QQ * HWXY)            // 655360 per-b
#define BQ (BB * QQ)              // 20

// Channel-last scratch: xt[(bq*HW + hw)*64 + c] == xf[b,c,n].
// Declared as float4 to guarantee 16B alignment for vector access.
__device__ float4 g_xt4[(size_t)BQ * HWXY * CC / 4];   // 335 MB

// ---------------------------------------------------------------------------
// Kernel 1: per-bq transpose (C=64, HW) -> (HW, C=64), float4 both directions
// block 256, tile 64(c) x 64(hw), grid (HW/64 = 1024, 1, BQ)
// ---------------------------------------------------------------------------
__global__ void __launch_bounds__(256)
transpose_kernel(const float* __restrict__ x, float* __restrict__ xt)
{
    __shared__ __align__(16) float tile[CC][65];

    const int t   = threadIdx.x;
    const int hw0 = blockIdx.x * 64;
    const size_t inbase = (size_t)blockIdx.z * CC * HWXY;

    // Load: 64 rows x 16 float4 (1024 slots), 4 per thread. 256B runs per row.
    #pragma unroll
    for (int j = 0; j < 4; j++) {
        const int linear = t + 256 * j;
        const int c  = linear >> 4;
        const int f4 = linear & 15;
        const float4 v = *(const float4*)&x[inbase + (size_t)c * HWXY + hw0 + f4 * 4];
        tile[c][f4 * 4 + 0] = v.x;
        tile[c][f4 * 4 + 1] = v.y;
        tile[c][f4 * 4 + 2] = v.z;
        tile[c][f4 * 4 + 3] = v.w;
    }
    __syncthreads();

    // Store: 64 n-rows x 16 float4 (c-direction), perfectly coalesced 256B runs.
    const size_t outbase = ((size_t)blockIdx.z * HWXY + hw0) * CC;
    #pragma unroll
    for (int j = 0; j < 4; j++) {
        const int linear = t + 256 * j;
        const int n   = linear >> 4;
        const int cf4 = linear & 15;
        const int c0  = cf4 * 4;
        float4 v;
        v.x = tile[c0 + 0][n];
        v.y = tile[c0 + 1][n];
        v.z = tile[c0 + 2][n];
        v.w = tile[c0 + 3][n];
        *(float4*)&xt[outbase + (size_t)n * CC + c0] = v;
    }
}

// ---------------------------------------------------------------------------
// Kernel 2: fused gather + mean/max + attention + K-contraction
// block 256 = 8 warps; each warp handles 4 consecutive l -> block covers 32 l.
// Output staged through smem and written as coalesced float4 lines.
// grid: (LL/32 = 2025, BB)
// ---------------------------------------------------------------------------
__global__ void __launch_bounds__(256)
fused_kernel(const float* __restrict__ xt,
             const void* __restrict__ idx_raw,  // (64800,9) int32 OR int64
             const float* __restrict__ att_w,   // (9,2,9)
             const float* __restrict__ att_b,   // (9,)
             const float* __restrict__ tc_w,    // (64,9)
             const float* __restrict__ tc_b,    // (64,)
             float* __restrict__ out)           // (B, 64, L)
{
    __shared__ __align__(16) float s_out[CC][36];  // float4-aligned rows (144B stride)
    __shared__ float s_aw[KK * 2 * KK];            // 162
    __shared__ float s_ab[KK];

    const int tid = threadIdx.x;
    if (tid < KK * 2 * KK) s_aw[tid] = att_w[tid];
    if (tid < KK)          s_ab[tid] = att_b[tid];
    __syncthreads();

    // ---- dtype sniff: int64 values < 2^31 have zero high words at odd
    // 32-bit positions; int32 indices there are random in [0, 655360).
    const int* __restrict__ i32 = (const int*)idx_raw;
    const bool is64 = (i32[1] | i32[3] | i32[5] | i32[7] |
                       i32[9] | i32[11] | i32[13] | i32[15]) == 0;

    const int warp = tid >> 5;
    const int lane = tid & 31;
    const int b    = blockIdx.y;
    const int lblk = blockIdx.x * 32;       // first l of this block
    const int l0   = lblk + warp * 4;       // first l of this warp

    // per-lane channels + hoisted contraction weights
    const int c0 = lane * 2;
    float w0[KK], w1[KK];
    #pragma unroll
    for (int k = 0; k < KK; k++) {
        w0[k] = __ldg(&tc_w[c0 * KK + k]);
        w1[k] = __ldg(&tc_w[(c0 + 1) * KK + k]);
    }
    const float bias0 = __ldg(&tc_b[c0]);
    const float bias1 = __ldg(&tc_b[c0 + 1]);

    const float2* __restrict__ xt2 = (const float2*)xt;

    #pragma unroll
    for (int j = 0; j < 4; j++) {
        const int l = l0 + j;

        int nk = 0;
        if (lane < KK) {
            const size_t pos = (size_t)l * KK + lane;
            nk = is64 ? (int)((const long long*)idx_raw)[pos] : i32[pos];
        }

        // gather: 9 coalesced 256B column reads, lane owns channels c0, c0+1
        float2 v[KK];
        #pragma unroll
        for (int k = 0; k < KK; k++) {
            const int n = __shfl_sync(0xffffffffu, nk, k);
            v[k] = xt2[((size_t)b * NN + (size_t)n) * 32 + lane];
        }

        // mean / max over C via butterfly
        float mean_s[KK], max_s[KK];
        #pragma unroll
        for (int k = 0; k < KK; k++) {
            float s = v[k].x + v[k].y;
            float m = fmaxf(v[k].x, v[k].y);
            #pragma unroll
            for (int o = 16; o; o >>= 1) {
                s += __shfl_xor_sync(0xffffffffu, s, o);
                m  = fmaxf(m, __shfl_xor_sync(0xffffffffu, m, o));
            }
            mean_s[k] = s * (1.0f / 64.0f);
            max_s[k]  = m;
        }

        // lanes 0..8 compute sigmoid gates; broadcast scales
        float att = 0.0f;
        if (lane < KK) {
            float z = s_ab[lane];
            #pragma unroll
            for (int k = 0; k < KK; k++) {
                z = fmaf(mean_s[k], s_aw[lane * 18 + k],     z);
                z = fmaf(max_s[k],  s_aw[lane * 18 + 9 + k], z);
            }
            att = 1.0f / (1.0f + __expf(-z));
        }

        float o0 = bias0, o1 = bias1;
        #pragma unroll
        for (int k = 0; k < KK; k++) {
            const float sc = 1.0f + __shfl_sync(0xffffffffu, att, k);
            o0 = fmaf(v[k].x * sc, w0[k], o0);
            o1 = fmaf(v[k].y * sc, w1[k], o1);
        }

        const int ll = warp * 4 + j;
        s_out[c0][ll]     = o0;
        s_out[c0 + 1][ll] = o1;
    }
    __syncthreads();

    // Coalesced output: 64 rows x 8 float4; each 128B line fully covered.
    #pragma unroll
    for (int s = tid; s < 512; s += 256) {
        const int c = s >> 3;
        const int q = s & 7;
        const float4 vv = *(const float4*)&s_out[c][q * 4];
        *(float4*)&out[((size_t)(b * CC + c)) * LL + lblk + q * 4] = vv;
    }
}

// ---------------------------------------------------------------------------
extern "C" void kernel_launch(void* const* d_in, const int* in_sizes, int n_in,
                              void* d_out, int out_size)
{
    const float* x     = (const float*)d_in[0];      // (20, 64, 256, 256)
    const void*  idx   = d_in[1];                    // (64800, 9) int32 or int64
    const float* att_w = (const float*)d_in[2];      // (9,2,9)
    const float* att_b = (const float*)d_in[3];      // (9,)
    const float* tc_w  = (const float*)d_in[4];      // (64,9)
    const float* tc_b  = (const float*)d_in[5];      // (64,)
    float*       out   = (float*)d_out;              // (2, 64, 180, 360)

    float* xt;
    cudaGetSymbolAddress((void**)&xt, g_xt4);

    {
        dim3 grid(HWXY / 64, 1, BQ);
        transpose_kernel<<<grid, 256>>>(x, xt);
    }
    {
        dim3 grid(LL / 32, BB);
        fused_kernel<<<grid, 256>>>(xt, idx, att_w, att_b, tc_w, tc_b, out);
    }
}

// round 7
// speedup vs baseline: 2.0168x; 1.1883x over previous
#include <cuda_runtime.h>
#include <cuda_fp16.h>
#include <cstdint>

// Problem constants
#define BB 2
#define QQ 10
#define CC 64
#define HH 256
#define WW 256
#define HWXY (HH * WW)            // 65536
#define KK 9
#define LL 64800                  // 180*360
#define NN (QQ * HWXY)            // 655360 per-b
#define BQ (BB * QQ)              // 20

// fp16 channel-last scratch: row n holds 64 halfs (128B) = 8 uint4
__device__ uint4  g_xt16[(size_t)BQ * HWXY * 8];     // 167.8 MB
// per-n channel stats (mean, max) in fp32
__device__ float2 g_stats[(size_t)BQ * HWXY];        // 10.5 MB

// ---------------------------------------------------------------------------
// Kernel 1: per-bq transpose (C=64, HW) -> (HW, C=64) in fp16  +  channel stats
// block 256, tile 64(c) x 64(hw), grid (HW/64 = 1024, 1, BQ)
// ---------------------------------------------------------------------------
__global__ void __launch_bounds__(256)
transpose_stats_kernel(const float* __restrict__ x,
                       uint4* __restrict__ xt,
                       float2* __restrict__ stats)
{
    __shared__ __align__(16) float tile[CC][65];

    const int t   = threadIdx.x;
    const int hw0 = blockIdx.x * 64;
    const int bq  = blockIdx.z;
    const size_t inbase = (size_t)bq * CC * HWXY;

    // Load: 64 c-rows x 16 float4, coalesced 256B runs
    #pragma unroll
    for (int j = 0; j < 4; j++) {
        const int linear = t + 256 * j;
        const int c  = linear >> 4;
        const int f4 = linear & 15;
        const float4 v = *(const float4*)&x[inbase + (size_t)c * HWXY + hw0 + f4 * 4];
        tile[c][f4 * 4 + 0] = v.x;
        tile[c][f4 * 4 + 1] = v.y;
        tile[c][f4 * 4 + 2] = v.z;
        tile[c][f4 * 4 + 3] = v.w;
    }
    __syncthreads();

    // Store: 64 n-rows x 8 uint4 (8 halfs each), perfectly coalesced 128B rows
    const size_t outbase = ((size_t)bq * HWXY + hw0) * 8;   // uint4 units
    #pragma unroll
    for (int j = 0; j < 2; j++) {
        const int s = t + 256 * j;
        const int n = s >> 3;
        const int g = s & 7;
        const int c0 = g * 8;
        __half2 h0 = __floats2half2_rn(tile[c0 + 0][n], tile[c0 + 1][n]);
        __half2 h1 = __floats2half2_rn(tile[c0 + 2][n], tile[c0 + 3][n]);
        __half2 h2 = __floats2half2_rn(tile[c0 + 4][n], tile[c0 + 5][n]);
        __half2 h3 = __floats2half2_rn(tile[c0 + 6][n], tile[c0 + 7][n]);
        uint4 u;
        u.x = *(const unsigned*)&h0;
        u.y = *(const unsigned*)&h1;
        u.z = *(const unsigned*)&h2;
        u.w = *(const unsigned*)&h3;
        xt[outbase + (size_t)n * 8 + g] = u;
    }

    // Stats: mean/max over c per hw. 4 lanes per hw, 16 c each + 2 shuffle steps.
    {
        const int hw = t >> 2;
        const int q  = t & 3;
        float s = tile[q * 16][hw];
        float m = s;
        #pragma unroll
        for (int i = 1; i < 16; i++) {
            const float v = tile[q * 16 + i][hw];
            s += v;
            m  = fmaxf(m, v);
        }
        s += __shfl_xor_sync(0xffffffffu, s, 1);
        m  = fmaxf(m, __shfl_xor_sync(0xffffffffu, m, 1));
        s += __shfl_xor_sync(0xffffffffu, s, 2);
        m  = fmaxf(m, __shfl_xor_sync(0xffffffffu, m, 2));
        if (q == 0)
            stats[(size_t)bq * HWXY + hw0 + hw] = make_float2(s * (1.0f / 64.0f), m);
    }
}

// ---------------------------------------------------------------------------
// Kernel 2: fused gather + gates + K-contraction. Zero shuffles.
// block 256 = 8 warps; warp handles 4 l; block covers 32 consecutive l.
// grid: (LL/32 = 2025, BB)
// ---------------------------------------------------------------------------
__global__ void __launch_bounds__(256)
fused_kernel(const uint* __restrict__ xt16,      // half2 view of scratch
             const float2* __restrict__ stats,
             const void* __restrict__ idx_raw,   // (64800,9) int32 OR int64
             const float* __restrict__ att_w,    // (9,2,9)
             const float* __restrict__ att_b,    // (9,)
             const float* __restrict__ tc_w,     // (64,9)
             const float* __restrict__ tc_b,     // (64,)
             float* __restrict__ out)            // (B, 64, L)
{
    __shared__ int   s_idx[32 * KK];
    __shared__ float s_gate[32 * KK];
    __shared__ float s_aw[KK * 2 * KK];
    __shared__ float s_ab[KK];
    __shared__ __align__(16) float s_out[CC][36];

    const int tid = threadIdx.x;
    if (tid < KK * 2 * KK) s_aw[tid] = att_w[tid];
    if (tid < KK)          s_ab[tid] = att_b[tid];

    // dtype sniff: int64 values < 2^31 have zero high words at odd 32-bit slots
    const int* __restrict__ i32 = (const int*)idx_raw;
    const bool is64 = (i32[1] | i32[3] | i32[5] | i32[7] |
                       i32[9] | i32[11] | i32[13] | i32[15]) == 0;

    const int b    = blockIdx.y;
    const int lblk = blockIdx.x * 32;

    // Stage the block's 288 indices (coalesced)
    for (int s = tid; s < 32 * KK; s += 256) {
        const size_t pos = (size_t)lblk * KK + s;
        s_idx[s] = is64 ? (int)((const long long*)idx_raw)[pos] : i32[pos];
    }
    __syncthreads();

    // Gate phase: one thread per (l, gate i). Stats live in L2 (10.5 MB set).
    for (int p = tid; p < 32 * KK; p += 256) {
        const int ll = p / KK;
        const int i  = p - ll * KK;
        float z = s_ab[i];
        #pragma unroll
        for (int k = 0; k < KK; k++) {
            const float2 st = stats[(size_t)b * NN + s_idx[ll * KK + k]];
            z = fmaf(st.x, s_aw[i * 18 + k],     z);
            z = fmaf(st.y, s_aw[i * 18 + 9 + k], z);
        }
        s_gate[p] = 1.0f + 1.0f / (1.0f + __expf(-z));
    }
    __syncthreads();

    const int warp = tid >> 5;
    const int lane = tid & 31;
    const int c0   = lane * 2;

    float w0[KK], w1[KK];
    #pragma unroll
    for (int k = 0; k < KK; k++) {
        w0[k] = __ldg(&tc_w[c0 * KK + k]);
        w1[k] = __ldg(&tc_w[(c0 + 1) * KK + k]);
    }
    const float bias0 = __ldg(&tc_b[c0]);
    const float bias1 = __ldg(&tc_b[c0 + 1]);

    #pragma unroll
    for (int j = 0; j < 4; j++) {
        const int ll = warp * 4 + j;

        // gather: 9 coalesced 128B fp16 column reads (lane holds half2 = 2 ch)
        uint vu[KK];
        #pragma unroll
        for (int k = 0; k < KK; k++) {
            const int n = s_idx[ll * KK + k];          // LDS broadcast
            vu[k] = xt16[((size_t)b * NN + (size_t)n) * 32 + lane];
        }

        float o0 = bias0, o1 = bias1;
        #pragma unroll
        for (int k = 0; k < KK; k++) {
            const float2 v  = __half22float2(*(const __half2*)&vu[k]);
            const float  sc = s_gate[ll * KK + k];     // LDS broadcast
            o0 = fmaf(v.x * sc, w0[k], o0);
            o1 = fmaf(v.y * sc, w1[k], o1);
        }

        s_out[c0][ll]     = o0;
        s_out[c0 + 1][ll] = o1;
    }
    __syncthreads();

    // Coalesced output: 64 rows x 8 float4, full 128B lines
    #pragma unroll
    for (int s = tid; s < 512; s += 256) {
        const int c = s >> 3;
        const int q = s & 7;
        const float4 vv = *(const float4*)&s_out[c][q * 4];
        *(float4*)&out[((size_t)(b * CC + c)) * LL + lblk + q * 4] = vv;
    }
}

// ---------------------------------------------------------------------------
extern "C" void kernel_launch(void* const* d_in, const int* in_sizes, int n_in,
                              void* d_out, int out_size)
{
    const float* x     = (const float*)d_in[0];      // (20, 64, 256, 256)
    const void*  idx   = d_in[1];                    // (64800, 9) int32 or int64
    const float* att_w = (const float*)d_in[2];      // (9,2,9)
    const float* att_b = (const float*)d_in[3];      // (9,)
    const float* tc_w  = (const float*)d_in[4];      // (64,9)
    const float* tc_b  = (const float*)d_in[5];      // (64,)
    float*       out   = (float*)d_out;              // (2, 64, 180, 360)

    uint4* xt;
    float2* stats;
    cudaGetSymbolAddress((void**)&xt, g_xt16);
    cudaGetSymbolAddress((void**)&stats, g_stats);

    {
        dim3 grid(HWXY / 64, 1, BQ);
        transpose_stats_kernel<<<grid, 256>>>(x, xt, stats);
    }
    {
        dim3 grid(LL / 32, BB);
        fused_kernel<<<grid, 256>>>((const uint*)xt, stats, idx,
                                    att_w, att_b, tc_w, tc_b, out);
    }
}

// round 8
// speedup vs baseline: 2.0976x; 1.0401x over previous
#include <cuda_runtime.h>
#include <cuda_fp16.h>
#include <cstdint>

// Problem constants
#define BB 2
#define QQ 10
#define CC 64
#define HH 256
#define WW 256
#define HWXY (HH * WW)            // 65536
#define KK 9
#define LL 64800                  // 180*360
#define NN (QQ * HWXY)            // 655360 per-b
#define BQ (BB * QQ)              // 20

// fp16 channel-last scratch: row n holds 64 halfs (128B) = 8 uint4
__device__ uint4  g_xt16[(size_t)BQ * HWXY * 8];     // 167.8 MB
// per-n channel stats (mean, max) in fp32
__device__ float2 g_stats[(size_t)BQ * HWXY];        // 10.5 MB

// ---------------------------------------------------------------------------
// Kernel 1: per-bq transpose (C=64, HW) -> (HW, C=64) in fp16  +  channel stats
// block 256, tile 64(c) x 64(hw), grid (HW/64 = 1024, 1, BQ)
// ---------------------------------------------------------------------------
__global__ void __launch_bounds__(256)
transpose_stats_kernel(const float* __restrict__ x,
                       uint4* __restrict__ xt,
                       float2* __restrict__ stats)
{
    __shared__ __align__(16) float tile[CC][65];

    const int t   = threadIdx.x;
    const int hw0 = blockIdx.x * 64;
    const int bq  = blockIdx.z;
    const size_t inbase = (size_t)bq * CC * HWXY;

    // Load: 64 c-rows x 16 float4, coalesced 256B runs
    #pragma unroll
    for (int j = 0; j < 4; j++) {
        const int linear = t + 256 * j;
        const int c  = linear >> 4;
        const int f4 = linear & 15;
        const float4 v = *(const float4*)&x[inbase + (size_t)c * HWXY + hw0 + f4 * 4];
        tile[c][f4 * 4 + 0] = v.x;
        tile[c][f4 * 4 + 1] = v.y;
        tile[c][f4 * 4 + 2] = v.z;
        tile[c][f4 * 4 + 3] = v.w;
    }
    __syncthreads();

    // Store: 64 n-rows x 8 uint4 (8 halfs each), perfectly coalesced 128B rows
    const size_t outbase = ((size_t)bq * HWXY + hw0) * 8;   // uint4 units
    #pragma unroll
    for (int j = 0; j < 2; j++) {
        const int s = t + 256 * j;
        const int n = s >> 3;
        const int g = s & 7;
        const int c0 = g * 8;
        __half2 h0 = __floats2half2_rn(tile[c0 + 0][n], tile[c0 + 1][n]);
        __half2 h1 = __floats2half2_rn(tile[c0 + 2][n], tile[c0 + 3][n]);
        __half2 h2 = __floats2half2_rn(tile[c0 + 4][n], tile[c0 + 5][n]);
        __half2 h3 = __floats2half2_rn(tile[c0 + 6][n], tile[c0 + 7][n]);
        uint4 u;
        u.x = *(const unsigned*)&h0;
        u.y = *(const unsigned*)&h1;
        u.z = *(const unsigned*)&h2;
        u.w = *(const unsigned*)&h3;
        xt[outbase + (size_t)n * 8 + g] = u;
    }

    // Stats: mean/max over c per hw. 4 lanes per hw, 16 c each + 2 shuffle steps.
    {
        const int hw = t >> 2;
        const int q  = t & 3;
        float s = tile[q * 16][hw];
        float m = s;
        #pragma unroll
        for (int i = 1; i < 16; i++) {
            const float v = tile[q * 16 + i][hw];
            s += v;
            m  = fmaxf(m, v);
        }
        s += __shfl_xor_sync(0xffffffffu, s, 1);
        m  = fmaxf(m, __shfl_xor_sync(0xffffffffu, m, 1));
        s += __shfl_xor_sync(0xffffffffu, s, 2);
        m  = fmaxf(m, __shfl_xor_sync(0xffffffffu, m, 2));
        if (q == 0)
            stats[(size_t)bq * HWXY + hw0 + hw] = make_float2(s * (1.0f / 64.0f), m);
    }
}

// ---------------------------------------------------------------------------
// Kernel 2: fused gather + gates + K-contraction. Warp-autonomous mainloop:
// no block barriers between memory phases; gather LDGs overlap gate compute.
// block 256 = 8 warps; warp handles 4 l; block covers 32 consecutive l.
// grid: (LL/32 = 2025, BB)
// ---------------------------------------------------------------------------
__global__ void __launch_bounds__(256)
fused_kernel(const uint* __restrict__ xt16,      // half2 view of scratch
             const float2* __restrict__ stats,
             const void* __restrict__ idx_raw,   // (64800,9) int32 OR int64
             const float* __restrict__ att_w,    // (9,2,9)
             const float* __restrict__ att_b,    // (9,)
             const float* __restrict__ tc_w,     // (64,9)
             const float* __restrict__ tc_b,     // (64,)
             float* __restrict__ out)            // (B, 64, L)
{
    __shared__ float s_aw[KK * 2 * KK];            // 162
    __shared__ float s_ab[KK];
    __shared__ __align__(16) float s_out[CC][36];

    const int tid = threadIdx.x;
    if (tid < KK * 2 * KK) s_aw[tid] = att_w[tid];
    if (tid < KK)          s_ab[tid] = att_b[tid];

    // dtype sniff: int64 values < 2^31 have zero high words at odd 32-bit slots
    const int* __restrict__ i32 = (const int*)idx_raw;
    const bool is64 = (i32[1] | i32[3] | i32[5] | i32[7] |
                       i32[9] | i32[11] | i32[13] | i32[15]) == 0;

    const int warp = tid >> 5;
    const int lane = tid & 31;
    const int b    = blockIdx.y;
    const int lblk = blockIdx.x * 32;
    const int c0   = lane * 2;

    // hoisted contraction weights (tiny, L1-resident)
    float w0[KK], w1[KK];
    #pragma unroll
    for (int k = 0; k < KK; k++) {
        w0[k] = __ldg(&tc_w[c0 * KK + k]);
        w1[k] = __ldg(&tc_w[(c0 + 1) * KK + k]);
    }
    const float bias0 = __ldg(&tc_b[c0]);
    const float bias1 = __ldg(&tc_b[c0 + 1]);

    __syncthreads();   // s_aw / s_ab ready

    #pragma unroll
    for (int j = 0; j < 4; j++) {
        const int l = lblk + warp * 4 + j;

        // lanes 0..8 load this l's indices; broadcast to all lanes
        int nk = 0;
        if (lane < KK) {
            const size_t pos = (size_t)l * KK + lane;
            nk = is64 ? (int)((const long long*)idx_raw)[pos] : i32[pos];
        }
        int n[KK];
        #pragma unroll
        for (int k = 0; k < KK; k++)
            n[k] = __shfl_sync(0xffffffffu, nk, k);

        // issue all 9 gather loads NOW (128B coalesced columns, fp16);
        // they stay in flight while we fetch stats and compute gates.
        uint vu[KK];
        #pragma unroll
        for (int k = 0; k < KK; k++)
            vu[k] = xt16[((size_t)b * NN + (size_t)n[k]) * 32 + lane];

        // lane k holds stats for its own n_k
        float2 st = make_float2(0.0f, 0.0f);
        if (lane < KK) st = __ldg(&stats[(size_t)b * NN + nk]);

        // gates: lane i < 9 accumulates over k via shuffles of st
        float z = (lane < KK) ? s_ab[lane] : 0.0f;
        #pragma unroll
        for (int k = 0; k < KK; k++) {
            const float mk = __shfl_sync(0xffffffffu, st.x, k);
            const float xk = __shfl_sync(0xffffffffu, st.y, k);
            if (lane < KK) {
                z = fmaf(mk, s_aw[lane * 18 + k],     z);
                z = fmaf(xk, s_aw[lane * 18 + 9 + k], z);
            }
        }
        const float att = 1.0f / (1.0f + __expf(-z));

        // contraction: scale broadcast + FMA against arrived gather data
        float o0 = bias0, o1 = bias1;
        #pragma unroll
        for (int k = 0; k < KK; k++) {
            const float sc = 1.0f + __shfl_sync(0xffffffffu, att, k);
            const float2 v = __half22float2(*(const __half2*)&vu[k]);
            o0 = fmaf(v.x * sc, w0[k], o0);
            o1 = fmaf(v.y * sc, w1[k], o1);
        }

        const int ll = warp * 4 + j;
        s_out[c0][ll]     = o0;
        s_out[c0 + 1][ll] = o1;
    }
    __syncthreads();

    // Coalesced output: 64 rows x 8 float4, full 128B lines
    #pragma unroll
    for (int s = tid; s < 512; s += 256) {
        const int c = s >> 3;
        const int q = s & 7;
        const float4 vv = *(const float4*)&s_out[c][q * 4];
        *(float4*)&out[((size_t)(b * CC + c)) * LL + lblk + q * 4] = vv;
    }
}

// ---------------------------------------------------------------------------
extern "C" void kernel_launch(void* const* d_in, const int* in_sizes, int n_in,
                              void* d_out, int out_size)
{
    const float* x     = (const float*)d_in[0];      // (20, 64, 256, 256)
    const void*  idx   = d_in[1];                    // (64800, 9) int32 or int64
    const float* att_w = (const float*)d_in[2];      // (9,2,9)
    const float* att_b = (const float*)d_in[3];      // (9,)
    const float* tc_w  = (const float*)d_in[4];      // (64,9)
    const float* tc_b  = (const float*)d_in[5];      // (64,)
    float*       out   = (float*)d_out;              // (2, 64, 180, 360)

    uint4* xt;
    float2* stats;
    cudaGetSymbolAddress((void**)&xt, g_xt16);
    cudaGetSymbolAddress((void**)&stats, g_stats);

    {
        dim3 grid(HWXY / 64, 1, BQ);
        transpose_stats_kernel<<<grid, 256>>>(x, xt, stats);
    }
    {
        dim3 grid(LL / 32, BB);
        fused_kernel<<<grid, 256>>>((const uint*)xt, stats, idx,
                                    att_w, att_b, tc_w, tc_b, out);
    }
}

// round 9
// speedup vs baseline: 2.1609x; 1.0302x over previous
#include <cuda_runtime.h>
#include <cuda_fp16.h>
#include <cstdint>

// Problem constants
#define BB 2
#define QQ 10
#define CC 64
#define HH 256
#define WW 256
#define HWXY (HH * WW)            // 65536
#define KK 9
#define LL 64800                  // 180*360
#define NN (QQ * HWXY)            // 655360 per-b
#define BQ (BB * QQ)              // 20

// fp16 channel-last scratch: row n holds 64 halfs (128B) = 8 uint4
__device__ uint4  g_xt16[(size_t)BQ * HWXY * 8];     // 167.8 MB
// per-n channel stats (mean, max) in fp32
__device__ float2 g_stats[(size_t)BQ * HWXY];        // 10.5 MB
// per-(b,l) record: [n0..n8, gatebits0..8, pad, pad]  (20 uints = 80B)
__device__ uint4  g_rec[(size_t)BB * LL * 5];        // 10.4 MB

// ---------------------------------------------------------------------------
// Kernel 1: per-bq transpose (C=64, HW) -> (HW, C=64) in fp16  +  channel stats
// block 256, tile 64(c) x 64(hw), grid (HW/64 = 1024, 1, BQ)
// ---------------------------------------------------------------------------
__global__ void __launch_bounds__(256)
transpose_stats_kernel(const float* __restrict__ x,
                       uint4* __restrict__ xt,
                       float2* __restrict__ stats)
{
    __shared__ __align__(16) float tile[CC][65];

    const int t   = threadIdx.x;
    const int hw0 = blockIdx.x * 64;
    const int bq  = blockIdx.z;
    const size_t inbase = (size_t)bq * CC * HWXY;

    // Load: 64 c-rows x 16 float4, coalesced 256B runs. Streaming (read-once).
    #pragma unroll
    for (int j = 0; j < 4; j++) {
        const int linear = t + 256 * j;
        const int c  = linear >> 4;
        const int f4 = linear & 15;
        const float4 v = __ldcs((const float4*)&x[inbase + (size_t)c * HWXY + hw0 + f4 * 4]);
        tile[c][f4 * 4 + 0] = v.x;
        tile[c][f4 * 4 + 1] = v.y;
        tile[c][f4 * 4 + 2] = v.z;
        tile[c][f4 * 4 + 3] = v.w;
    }
    __syncthreads();

    // Store: 64 n-rows x 8 uint4 (8 halfs each), perfectly coalesced 128B rows
    const size_t outbase = ((size_t)bq * HWXY + hw0) * 8;   // uint4 units
    #pragma unroll
    for (int j = 0; j < 2; j++) {
        const int s = t + 256 * j;
        const int n = s >> 3;
        const int g = s & 7;
        const int c0 = g * 8;
        __half2 h0 = __floats2half2_rn(tile[c0 + 0][n], tile[c0 + 1][n]);
        __half2 h1 = __floats2half2_rn(tile[c0 + 2][n], tile[c0 + 3][n]);
        __half2 h2 = __floats2half2_rn(tile[c0 + 4][n], tile[c0 + 5][n]);
        __half2 h3 = __floats2half2_rn(tile[c0 + 6][n], tile[c0 + 7][n]);
        uint4 u;
        u.x = *(const unsigned*)&h0;
        u.y = *(const unsigned*)&h1;
        u.z = *(const unsigned*)&h2;
        u.w = *(const unsigned*)&h3;
        xt[outbase + (size_t)n * 8 + g] = u;
    }

    // Stats: mean/max over c per hw. 4 lanes per hw, 16 c each + 2 shuffle steps.
    {
        const int hw = t >> 2;
        const int q  = t & 3;
        float s = tile[q * 16][hw];
        float m = s;
        #pragma unroll
        for (int i = 1; i < 16; i++) {
            const float v = tile[q * 16 + i][hw];
            s += v;
            m  = fmaxf(m, v);
        }
        s += __shfl_xor_sync(0xffffffffu, s, 1);
        m  = fmaxf(m, __shfl_xor_sync(0xffffffffu, m, 1));
        s += __shfl_xor_sync(0xffffffffu, s, 2);
        m  = fmaxf(m, __shfl_xor_sync(0xffffffffu, m, 2));
        if (q == 0)
            stats[(size_t)bq * HWXY + hw0 + hw] = make_float2(s * (1.0f / 64.0f), m);
    }
}

// ---------------------------------------------------------------------------
// Kernel 2: gate precompute. One thread per (b,l): read idx + stats, compute
// all 9 (1+sigmoid) gates, write packed record [n0..8, gate0..8, pad2].
// grid ((BB*LL+255)/256), block 256
// ---------------------------------------------------------------------------
__global__ void __launch_bounds__(256)
gate_kernel(const float2* __restrict__ stats,
            const void* __restrict__ idx_raw,   // (64800,9) int32 OR int64
            const float* __restrict__ att_w,    // (9,2,9)
            const float* __restrict__ att_b,    // (9,)
            unsigned* __restrict__ rec)         // (BB*LL, 20) uints
{
    __shared__ float s_aw[KK * 2 * KK];
    __shared__ float s_ab[KK];
    const int tid = threadIdx.x;
    if (tid < KK * 2 * KK) s_aw[tid] = att_w[tid];
    if (tid < KK)          s_ab[tid] = att_b[tid];
    __syncthreads();

    const int gid = blockIdx.x * 256 + tid;
    if (gid >= BB * LL) return;
    const int b = gid / LL;
    const int l = gid - b * LL;

    // dtype sniff: int64 values < 2^31 have zero high words at odd 32-bit slots
    const int* __restrict__ i32 = (const int*)idx_raw;
    const bool is64 = (i32[1] | i32[3] | i32[5] | i32[7] |
                       i32[9] | i32[11] | i32[13] | i32[15]) == 0;

    int n[KK];
    #pragma unroll
    for (int k = 0; k < KK; k++) {
        const size_t pos = (size_t)l * KK + k;
        n[k] = is64 ? (int)((const long long*)idx_raw)[pos] : i32[pos];
    }

    float mn[KK], mx[KK];
    #pragma unroll
    for (int k = 0; k < KK; k++) {
        const float2 st = __ldg(&stats[(size_t)b * NN + n[k]]);
        mn[k] = st.x;
        mx[k] = st.y;
    }

    unsigned r[20];
    #pragma unroll
    for (int k = 0; k < KK; k++) r[k] = (unsigned)n[k];
    #pragma unroll
    for (int i = 0; i < KK; i++) {
        float z = s_ab[i];
        #pragma unroll
        for (int k = 0; k < KK; k++) {
            z = fmaf(mn[k], s_aw[i * 18 + k],     z);
            z = fmaf(mx[k], s_aw[i * 18 + 9 + k], z);
        }
        const float g = 1.0f + 1.0f / (1.0f + __expf(-z));
        r[KK + i] = __float_as_uint(g);
    }
    r[18] = 0; r[19] = 0;

    uint4* __restrict__ rec4 = (uint4*)rec;
    const size_t base = (size_t)gid * 5;
    #pragma unroll
    for (int q = 0; q < 5; q++)
        rec4[base + q] = make_uint4(r[q*4], r[q*4+1], r[q*4+2], r[q*4+3]);
}

// ---------------------------------------------------------------------------
// Kernel 3: gather + contraction only. Per l: one record load + 18 shfl +
// 9 gather LDG + 18 FMA. block 256 = 8 warps x 4 l = 32 consecutive l.
// grid: (LL/32 = 2025, BB)
// ---------------------------------------------------------------------------
__global__ void __launch_bounds__(256)
fused_kernel(const uint* __restrict__ xt16,      // half2 view of scratch
             const unsigned* __restrict__ rec,   // (BB*LL, 20)
             const float* __restrict__ tc_w,     // (64,9)
             const float* __restrict__ tc_b,     // (64,)
             float* __restrict__ out)            // (B, 64, L)
{
    __shared__ __align__(16) float s_out[CC][36];

    const int tid  = threadIdx.x;
    const int warp = tid >> 5;
    const int lane = tid & 31;
    const int b    = blockIdx.y;
    const int lblk = blockIdx.x * 32;
    const int c0   = lane * 2;

    float w0[KK], w1[KK];
    #pragma unroll
    for (int k = 0; k < KK; k++) {
        w0[k] = __ldg(&tc_w[c0 * KK + k]);
        w1[k] = __ldg(&tc_w[(c0 + 1) * KK + k]);
    }
    const float bias0 = __ldg(&tc_b[c0]);
    const float bias1 = __ldg(&tc_b[c0 + 1]);

    #pragma unroll
    for (int j = 0; j < 4; j++) {
        const int l  = lblk + warp * 4 + j;
        const int ll = warp * 4 + j;

        // one 72B record read: lanes 0..8 -> n, lanes 9..17 -> gate
        unsigned r = 0;
        if (lane < 18) r = rec[((size_t)b * LL + l) * 20 + lane];

        // broadcast indices, issue all gathers immediately (stay in flight)
        int n[KK];
        #pragma unroll
        for (int k = 0; k < KK; k++)
            n[k] = (int)__shfl_sync(0xffffffffu, r, k);

        uint vu[KK];
        #pragma unroll
        for (int k = 0; k < KK; k++)
            vu[k] = xt16[((size_t)b * NN + (size_t)n[k]) * 32 + lane];

        float o0 = bias0, o1 = bias1;
        #pragma unroll
        for (int k = 0; k < KK; k++) {
            const float sc = __uint_as_float(__shfl_sync(0xffffffffu, r, KK + k));
            const float2 v = __half22float2(*(const __half2*)&vu[k]);
            o0 = fmaf(v.x * sc, w0[k], o0);
            o1 = fmaf(v.y * sc, w1[k], o1);
        }

        s_out[c0][ll]     = o0;
        s_out[c0 + 1][ll] = o1;
    }
    __syncthreads();

    // Coalesced output: 64 rows x 8 float4, full 128B lines
    #pragma unroll
    for (int s = tid; s < 512; s += 256) {
        const int c = s >> 3;
        const int q = s & 7;
        const float4 vv = *(const float4*)&s_out[c][q * 4];
        *(float4*)&out[((size_t)(b * CC + c)) * LL + lblk + q * 4] = vv;
    }
}

// ---------------------------------------------------------------------------
extern "C" void kernel_launch(void* const* d_in, const int* in_sizes, int n_in,
                              void* d_out, int out_size)
{
    const float* x     = (const float*)d_in[0];      // (20, 64, 256, 256)
    const void*  idx   = d_in[1];                    // (64800, 9) int32 or int64
    const float* att_w = (const float*)d_in[2];      // (9,2,9)
    const float* att_b = (const float*)d_in[3];      // (9,)
    const float* tc_w  = (const float*)d_in[4];      // (64,9)
    const float* tc_b  = (const float*)d_in[5];      // (64,)
    float*       out   = (float*)d_out;              // (2, 64, 180, 360)

    uint4* xt;  float2* stats;  uint4* rec;
    cudaGetSymbolAddress((void**)&xt, g_xt16);
    cudaGetSymbolAddress((void**)&stats, g_stats);
    cudaGetSymbolAddress((void**)&rec, g_rec);

    {
        dim3 grid(HWXY / 64, 1, BQ);
        transpose_stats_kernel<<<grid, 256>>>(x, xt, stats);
    }
    {
        dim3 grid((BB * LL + 255) / 256);
        gate_kernel<<<grid, 256>>>(stats, idx, att_w, att_b, (unsigned*)rec);
    }
    {
        dim3 grid(LL / 32, BB);
        fused_kernel<<<grid, 256>>>((const uint*)xt, (const unsigned*)rec,
                                    tc_w, tc_b, out);
    }
}